// round 11
// baseline (speedup 1.0000x reference)
#include <cuda_runtime.h>
#include <stdint.h>

#define Kb     256
#define Dd     128
#define KEMAX  256
#define Ff     1025
#define NROWS  1024
#define CSTR   (512*1025)
#define MW     96
#define NFP    1056
#define NPAIR  528
#define NBCOL  68

typedef unsigned long long ull;

// ---- static device scratch ----
__device__ float g_Weff[(size_t)Kb*KEMAX*KEMAX];
__device__ float g_beff[Kb*KEMAX];
__device__ int   g_flo[Kb], g_nz[Kb];
__device__ int   g_deg[NFP], g_bands[NFP*4];
__device__ int   g_fmin2[NPAIR], g_wid2[NPAIR];
__device__ int   g_bmin[NBCOL], g_bwid[NBCOL];
__device__ float g_M[(size_t)NPAIR*MW*32];   // [pair][j][s(2)][c(4)][c2(4)]
__device__ float g_bias[NFP*4];

__device__ __forceinline__ ull splat2(float v) {
    ull r; asm("mov.b64 %0, {%1, %1};" : "=l"(r) : "f"(v)); return r;
}
__device__ __forceinline__ void ffma2(ull& d, ull a, ull b) {
    asm("fma.rn.f32x2 %0, %1, %2, %0;" : "+l"(d) : "l"(a), "l"(b));
}
__device__ __forceinline__ void unpack2(ull v, float& lo, float& hi) {
    asm("mov.b64 {%0, %1}, %2;" : "=f"(lo), "=f"(hi) : "l"(v));
}

// ---------------------------------------------------------------------------
// k_finfo: band ranges + per-f' band list + per-pair [fmin,width) +
// per-block-col [bmin,bwid). 33 parallel blocks.
// ---------------------------------------------------------------------------
__global__ __launch_bounds__(256) void k_finfo(
    const int* __restrict__ nzidx, const float* __restrict__ mask, int Wb)
{
    __shared__ int s_flo[Kb], s_nz[Kb];
    __shared__ int s_fmf[32], s_fxf[32];
    __shared__ int s_pmn[16], s_pwd[16];
    const int tid = threadIdx.x;
    {
        int n = 0;
        for (int w = 0; w < Wb; ++w) n += (mask[tid*Wb + w] > 0.5f);
        int flo = nzidx[tid*Wb];
        s_flo[tid] = flo; s_nz[tid] = n;
        if (blockIdx.x == 0) { g_flo[tid] = flo; g_nz[tid] = n; }
    }
    __syncthreads();

    if (tid < 32) {
        int f = blockIdx.x*32 + tid;
        int deg = 0, bl[4] = {0,0,0,0};
        int fmn = 1<<29, fmx = -1;
        if (f < Ff) {
            for (int k = 0; k < Kb; ++k) {
                int w = f - s_flo[k];
                if (w >= 0 && w < s_nz[k]) {
                    if (deg < 4) bl[deg] = k;
                    ++deg;
                    fmn = min(fmn, s_flo[k]);
                    fmx = max(fmx, s_flo[k] + s_nz[k]);
                }
            }
        }
        deg = min(deg, 4);
        if (f < NFP) {
            g_deg[f] = deg;
            #pragma unroll
            for (int i = 0; i < 4; ++i) g_bands[f*4+i] = bl[i];
        }
        s_fmf[tid] = deg ? fmn : (1<<29);
        s_fxf[tid] = deg ? fmx : -1;
    }
    __syncthreads();
    if (tid < 16) {
        int p = blockIdx.x*16 + tid;
        int fmn = min(s_fmf[2*tid], s_fmf[2*tid+1]);
        int fmx = max(s_fxf[2*tid], s_fxf[2*tid+1]);
        int w;
        if (fmx < 0) { fmn = 0; w = 0; }
        else         { w = min(fmx - fmn, MW); }
        if (p < NPAIR) { g_fmin2[p] = fmn; g_wid2[p] = w; }
        s_pmn[tid] = fmn; s_pwd[tid] = w;
    }
    __syncthreads();
    if (tid < 2) {
        int bc = blockIdx.x*2 + tid;
        int mn = 1<<29, mx = -1;
        #pragma unroll
        for (int i = 0; i < 8; ++i) {
            int pl = tid*8 + i;
            if (s_pwd[pl] > 0) {
                mn = min(mn, s_pmn[pl]);
                mx = max(mx, s_pmn[pl] + s_pwd[pl]);
            }
        }
        if (bc < NBCOL) {
            if (mx < 0) { g_bmin[bc] = 0; g_bwid[bc] = 0; }
            else        { g_bmin[bc] = mn; g_bwid[bc] = mx - mn; }
        }
    }
}

// ---------------------------------------------------------------------------
// k_weff: per-band fused W1@W2 (mel, 1/ola folded). grid (Kb, itiles of 16).
// ---------------------------------------------------------------------------
__global__ __launch_bounds__(256) void k_weff(
    const float* __restrict__ W1, const float* __restrict__ b1,
    const float* __restrict__ W2, const float* __restrict__ b2,
    const int*   __restrict__ nzidx, const float* __restrict__ nzmel,
    const float* __restrict__ ola, int Wb)
{
    __shared__ float W1s[16*Dd];
    __shared__ float cs[KEMAX];
    __shared__ float rs[16];
    __shared__ float b1s[Dd];

    const int k     = blockIdx.x;
    const int KeW   = 4*Wb;
    const int iBase = blockIdx.y * 16;
    const int tid   = threadIdx.x;

    const int nnz = g_nz[k];
    const int Ke4 = 4*nnz;
    if (iBase >= Ke4) return;
    const int ni = min(16, Ke4 - iBase);

    for (int j = tid; j < ni*Dd; j += 256)
        W1s[j] = W1[((size_t)k*KeW + iBase)*Dd + j];
    for (int w = tid; w < nnz; w += 256) {
        float inv = 1.0f / ola[nzidx[k*Wb + w]];
        cs[4*w+0]=inv; cs[4*w+1]=inv; cs[4*w+2]=inv; cs[4*w+3]=inv;
    }
    if (tid < ni) rs[tid] = nzmel[k*Wb + ((iBase + tid) >> 2)];
    if (tid < Dd) b1s[tid] = b1[k*Dd + tid];
    __syncthreads();

    const int nct = Ke4 >> 2, nrt = ni >> 2;
    if (tid < nrt*nct) {
        const int tr = tid / nct, tc = tid - tr*nct;
        ull acc[4][2] = {{0,0},{0,0},{0,0},{0,0}};
        const float* a = &W1s[(tr*4)*Dd];
        const float* w2base = W2 + (size_t)k*Dd*KeW + tc*4;
        #pragma unroll 4
        for (int d = 0; d < Dd; ++d) {
            ulonglong2 bv = *reinterpret_cast<const ulonglong2*>(w2base + (size_t)d*KeW);
            ull s;
            s = splat2(a[d]);      ffma2(acc[0][0], s, bv.x); ffma2(acc[0][1], s, bv.y);
            s = splat2(a[Dd+d]);   ffma2(acc[1][0], s, bv.x); ffma2(acc[1][1], s, bv.y);
            s = splat2(a[2*Dd+d]); ffma2(acc[2][0], s, bv.x); ffma2(acc[2][1], s, bv.y);
            s = splat2(a[3*Dd+d]); ffma2(acc[3][0], s, bv.x); ffma2(acc[3][1], s, bv.y);
        }
        const int gi = iBase + tr*4, go = tc*4;
        float4 c4 = *reinterpret_cast<const float4*>(&cs[go]);
        #pragma unroll
        for (int rr = 0; rr < 4; ++rr) {
            float v0,v1,v2,v3;
            unpack2(acc[rr][0], v0, v1);
            unpack2(acc[rr][1], v2, v3);
            float r = rs[tr*4+rr];
            float4 o4 = make_float4(v0*r*c4.x, v1*r*c4.y, v2*r*c4.z, v3*r*c4.w);
            *reinterpret_cast<float4*>(&g_Weff[((size_t)k*KeW + gi+rr)*KeW + go]) = o4;
        }
    }

    if (blockIdx.y == 0) {
        for (int o = tid; o < Ke4; o += 256) {
            float s = b2[(size_t)k*KeW + o];
            for (int d = 0; d < Dd; ++d) s += b1s[d] * W2[((size_t)k*Dd + d)*KeW + o];
            g_beff[k*KEMAX + o] = s * cs[o];
        }
    }
}

// ---------------------------------------------------------------------------
// k_scatter: assemble banded rows of M in pair-interleaved layout
//   g_M[((p*MW + j)*2 + s)*16 + c*4 + c2],  s = f&1
// ---------------------------------------------------------------------------
__global__ __launch_bounds__(256) void k_scatter(int Wb)
{
    const int f   = blockIdx.x;
    const int KeW = 4*Wb;
    const int p   = f >> 1;
    const int s   = f & 1;
    const int fm2 = g_fmin2[p];
    const int wid = g_wid2[p];
    const int deg = g_deg[f];
    __shared__ int s_k[4], s_flo4[4], s_nz4[4], s_wp[4];
    if (threadIdx.x < 4) {
        int i = threadIdx.x;
        int k = g_bands[f*4 + i];
        s_k[i]    = k;
        s_flo4[i] = g_flo[k];
        s_nz4[i]  = g_nz[k];
        s_wp[i]   = f - g_flo[k];
    }
    __syncthreads();

    for (int pos = threadIdx.x; pos < wid*4; pos += 256) {
        int j = pos >> 2;
        int c = pos & 3;
        int fbin = fm2 + j;
        float4 u[4];
        #pragma unroll
        for (int d = 0; d < 4; ++d) {
            int w = fbin - s_flo4[d];
            bool pv = (d < deg) && (w >= 0) && (w < s_nz4[d]);
            u[d] = pv ? *reinterpret_cast<const float4*>(
                     &g_Weff[((size_t)s_k[d]*KeW + 4*w + c)*KeW + 4*s_wp[d]])
                      : make_float4(0.f,0.f,0.f,0.f);
        }
        float4 v;
        v.x = (u[0].x + u[1].x) + (u[2].x + u[3].x);
        v.y = (u[0].y + u[1].y) + (u[2].y + u[3].y);
        v.z = (u[0].z + u[1].z) + (u[2].z + u[3].z);
        v.w = (u[0].w + u[1].w) + (u[2].w + u[3].w);
        *reinterpret_cast<float4*>(
            &g_M[(((size_t)p*MW + j)*2 + s)*16 + c*4]) = v;
    }
    if (threadIdx.x < 4) {
        float v = 0.0f;
        for (int d = 0; d < deg; ++d)
            v += g_beff[s_k[d]*KEMAX + 4*s_wp[d] + threadIdx.x];
        g_bias[f*4 + threadIdx.x] = v;
    }
}

// ---------------------------------------------------------------------------
// k_main: block = 64 rows x 16 f'; warp = 1 f'-pair; lane = 1 row-pair.
// M staged into smem (coalesced once per block), inner loop reads M via
// broadcast LDS.128 (29cyc, no L1 misses). 1 block/SM, 8 warps.
// ---------------------------------------------------------------------------
__global__ __launch_bounds__(256) void k_main(
    const float* __restrict__ x, float* __restrict__ out, int sstr)
{
    extern __shared__ __align__(16) float smx[];   // [32 rowpairs][sstr] then M
    float* smo = smx;                              // aliases x region at epilogue
    float* Msm = smx + 32*sstr;                    // [8 pairs][MW][32 floats]

    const int tid   = threadIdx.x;
    const int wrp   = tid >> 5, lane = tid & 31;
    const int f0    = blockIdx.x * 16;
    const int p0    = f0 >> 1;
    const int row0  = blockIdx.y * 64;
    const int bmin  = g_bmin[blockIdx.x];
    const int bwid  = g_bwid[blockIdx.x];

    // ---- stage M for the 8 pairs (coalesced float4 copy, live rows only)
    {
        const float4* gm4 = reinterpret_cast<const float4*>(g_M) + (size_t)p0*MW*8;
        float4* Msm4 = reinterpret_cast<float4*>(Msm);
        #pragma unroll
        for (int q = 0; q < 8; ++q) {
            int n = g_wid2[p0 + q] * 8;
            for (int i = tid; i < n; i += 256)
                Msm4[q*MW*8 + i] = gm4[(size_t)q*MW*8 + i];
        }
    }

    // ---- stage x: warp wrp stages rowpairs 4*wrp..4*wrp+3; lanes stride bins.
    #pragma unroll
    for (int q = 0; q < 4; ++q) {
        const int rp  = wrp*4 + q;
        const int rowE = row0 + 2*rp, rowO = rowE + 1;
        const int bE = rowE >> 9, tE = rowE & 511;
        const int bO = rowO >> 9, tO = rowO & 511;
        const float* xe = x + ((size_t)(bE*4)*512 + tE)*Ff + bmin;
        const float* xo = x + ((size_t)(bO*4)*512 + tO)*Ff + bmin;
        float* dst = smx + rp*sstr;
        for (int u = lane; u < bwid; u += 32) {
            float4 ve = make_float4(xe[u], xe[u+CSTR], xe[u+(size_t)2*CSTR], xe[u+(size_t)3*CSTR]);
            float4 vo = make_float4(xo[u], xo[u+CSTR], xo[u+(size_t)2*CSTR], xo[u+(size_t)3*CSTR]);
            *reinterpret_cast<float4*>(dst + u*8)     = ve;
            *reinterpret_cast<float4*>(dst + u*8 + 4) = vo;
        }
    }
    __syncthreads();

    const int p    = p0 + wrp;
    const int jmax = g_wid2[p];
    const int u0   = g_fmin2[p] - bmin;
    const int fA   = 2*p;

    const ulonglong2* mbase =
        reinterpret_cast<const ulonglong2*>(Msm) + (size_t)wrp*MW*8;
    ulonglong2 bAv = *reinterpret_cast<const ulonglong2*>(&g_bias[fA*4]);
    ulonglong2 bBv = *reinterpret_cast<const ulonglong2*>(&g_bias[fA*4 + 4]);

    // acc[row2][f'2][c2pair2] as named regs
    ull aE00 = bAv.x, aE01 = bAv.y, aE10 = bBv.x, aE11 = bBv.y;
    ull aO00 = bAv.x, aO01 = bAv.y, aO10 = bBv.x, aO11 = bBv.y;

    const float* xp = smx + lane*sstr + u0*8;

    ulonglong2 Ms[2][8];
    float4 Xe[2], Xo[2];

    #define PREF(S, JJ) { \
        int _j = (JJ); if (_j >= jmax) _j = jmax - 1; \
        const ulonglong2* _m = mbase + _j*8; \
        Ms[S][0]=_m[0]; Ms[S][1]=_m[1]; Ms[S][2]=_m[2]; Ms[S][3]=_m[3]; \
        Ms[S][4]=_m[4]; Ms[S][5]=_m[5]; Ms[S][6]=_m[6]; Ms[S][7]=_m[7]; \
        const float* _x = xp + _j*8; \
        Xe[S] = *reinterpret_cast<const float4*>(_x); \
        Xo[S] = *reinterpret_cast<const float4*>(_x + 4); }

    #define COMPUTE(S) { \
        ull s_; \
        s_ = splat2(Xe[S].x); \
        ffma2(aE00, s_, Ms[S][0].x); ffma2(aE01, s_, Ms[S][0].y); \
        ffma2(aE10, s_, Ms[S][4].x); ffma2(aE11, s_, Ms[S][4].y); \
        s_ = splat2(Xe[S].y); \
        ffma2(aE00, s_, Ms[S][1].x); ffma2(aE01, s_, Ms[S][1].y); \
        ffma2(aE10, s_, Ms[S][5].x); ffma2(aE11, s_, Ms[S][5].y); \
        s_ = splat2(Xe[S].z); \
        ffma2(aE00, s_, Ms[S][2].x); ffma2(aE01, s_, Ms[S][2].y); \
        ffma2(aE10, s_, Ms[S][6].x); ffma2(aE11, s_, Ms[S][6].y); \
        s_ = splat2(Xe[S].w); \
        ffma2(aE00, s_, Ms[S][3].x); ffma2(aE01, s_, Ms[S][3].y); \
        ffma2(aE10, s_, Ms[S][7].x); ffma2(aE11, s_, Ms[S][7].y); \
        s_ = splat2(Xo[S].x); \
        ffma2(aO00, s_, Ms[S][0].x); ffma2(aO01, s_, Ms[S][0].y); \
        ffma2(aO10, s_, Ms[S][4].x); ffma2(aO11, s_, Ms[S][4].y); \
        s_ = splat2(Xo[S].y); \
        ffma2(aO00, s_, Ms[S][1].x); ffma2(aO01, s_, Ms[S][1].y); \
        ffma2(aO10, s_, Ms[S][5].x); ffma2(aO11, s_, Ms[S][5].y); \
        s_ = splat2(Xo[S].z); \
        ffma2(aO00, s_, Ms[S][2].x); ffma2(aO01, s_, Ms[S][2].y); \
        ffma2(aO10, s_, Ms[S][6].x); ffma2(aO11, s_, Ms[S][6].y); \
        s_ = splat2(Xo[S].w); \
        ffma2(aO00, s_, Ms[S][3].x); ffma2(aO01, s_, Ms[S][3].y); \
        ffma2(aO10, s_, Ms[S][7].x); ffma2(aO11, s_, Ms[S][7].y); }

    if (jmax > 0) {
        PREF(0, 0)
        PREF(1, 1)
        int j = 0;
        for (; j + 1 < jmax; j += 2) {
            COMPUTE(0)
            PREF(0, j + 2)
            COMPUTE(1)
            PREF(1, j + 3)
        }
        if (j < jmax) COMPUTE(0)          // odd tail (slot0 holds j = jmax-1)
    }
    #undef PREF
    #undef COMPUTE

    __syncthreads();   // x tile dead; smo aliases smx

    // stage results: smo[row(64)][c2(4)*17 + fx(16)]
    {
        int rowl = 2*lane;
        float v0,v1,v2,v3;
        #pragma unroll
        for (int g = 0; g < 2; ++g) {
            int fx = 2*wrp + g;
            ull a0 = g ? aE10 : aE00, a1 = g ? aE11 : aE01;
            unpack2(a0, v0, v1); unpack2(a1, v2, v3);
            smo[rowl*69 + 0*17 + fx] = v0;
            smo[rowl*69 + 1*17 + fx] = v1;
            smo[rowl*69 + 2*17 + fx] = v2;
            smo[rowl*69 + 3*17 + fx] = v3;
            ull b0 = g ? aO10 : aO00, b1 = g ? aO11 : aO01;
            unpack2(b0, v0, v1); unpack2(b1, v2, v3);
            smo[(rowl+1)*69 + 0*17 + fx] = v0;
            smo[(rowl+1)*69 + 1*17 + fx] = v1;
            smo[(rowl+1)*69 + 2*17 + fx] = v2;
            smo[(rowl+1)*69 + 3*17 + fx] = v3;
        }
    }
    __syncthreads();

    // coalesced store: warp wrp covers rows 8*wrp..8*wrp+7
    #pragma unroll
    for (int rr = 0; rr < 8; ++rr) {
        const int r   = wrp*8 + rr;
        const int row = row0 + r, b = row >> 9, t = row & 511;
        #pragma unroll
        for (int h = 0; h < 2; ++h) {
            int e   = h*32 + lane;          // 0..63
            int fx  = e & 15, cc2 = e >> 4;
            int f = f0 + fx;
            if (f < Ff)
                out[((size_t)(b*4 + cc2)*512 + t)*Ff + f] = smo[r*69 + cc2*17 + fx];
        }
    }
}

// ---------------------------------------------------------------------------
extern "C" void kernel_launch(void* const* d_in, const int* in_sizes, int n_in,
                              void* d_out, int out_size)
{
    const float* x     = (const float*)d_in[0];
    const float* W1    = (const float*)d_in[1];
    const float* b1    = (const float*)d_in[2];
    const float* W2    = (const float*)d_in[3];
    const float* b2    = (const float*)d_in[4];
    const int*   nzidx = (const int*)  d_in[5];
    const float* nzmel = (const float*)d_in[6];
    const float* mask  = (const float*)d_in[7];
    const float* ola   = (const float*)d_in[8];

    const int Wb = in_sizes[5] / Kb;

    k_finfo<<<33, 256>>>(nzidx, mask, Wb);

    int gy = (4*Wb + 15) / 16;
    k_weff<<<dim3(Kb, gy), 256>>>(W1, b1, W2, b2, nzidx, nzmel, ola, Wb);

    k_scatter<<<NFP, 256>>>(Wb);

    int xrange = 2*Wb + 16;
    int sstr = 8*xrange + 4;                     // floats per rowpair
    int main_smem = (32*sstr + 8*MW*32) * (int)sizeof(float);
    int smo_need = 64*69*(int)sizeof(float);
    if (main_smem < smo_need) main_smem = smo_need;
    cudaFuncSetAttribute(k_main, cudaFuncAttributeMaxDynamicSharedMemorySize, main_smem);
    k_main<<<dim3((Ff + 15)/16, NROWS/64), 256, main_smem>>>(x, (float*)d_out, sstr);
}

// round 12
// speedup vs baseline: 1.0340x; 1.0340x over previous
#include <cuda_runtime.h>
#include <stdint.h>

#define Kb     256
#define Dd     128
#define KEMAX  256
#define Ff     1025
#define NROWS  1024
#define CSTR   (512*1025)
#define MW     96
#define NFP    1056
#define NPAIR  528
#define NBCOL  132

typedef unsigned long long ull;

// ---- static device scratch ----
__device__ float g_Weff[(size_t)Kb*KEMAX*KEMAX];
__device__ float g_beff[Kb*KEMAX];
__device__ int   g_flo[Kb], g_nz[Kb];
__device__ int   g_deg[NFP], g_bands[NFP*4];
__device__ int   g_fmin2[NPAIR], g_wid2[NPAIR];
__device__ int   g_bmin[NBCOL], g_bwid[NBCOL];
__device__ float g_M[(size_t)NPAIR*MW*32];   // [pair][j][s(2)][c(4)][c2(4)]
__device__ float g_bias[NFP*4];

__device__ __forceinline__ ull splat2(float v) {
    ull r; asm("mov.b64 %0, {%1, %1};" : "=l"(r) : "f"(v)); return r;
}
__device__ __forceinline__ void ffma2(ull& d, ull a, ull b) {
    asm("fma.rn.f32x2 %0, %1, %2, %0;" : "+l"(d) : "l"(a), "l"(b));
}
__device__ __forceinline__ void unpack2(ull v, float& lo, float& hi) {
    asm("mov.b64 {%0, %1}, %2;" : "=f"(lo), "=f"(hi) : "l"(v));
}

// ---------------------------------------------------------------------------
// k_finfo: band ranges + per-f' band list + per-pair [fmin,width) +
// per-block-col (8 f' granularity) [bmin,bwid). 33 parallel blocks.
// ---------------------------------------------------------------------------
__global__ __launch_bounds__(256) void k_finfo(
    const int* __restrict__ nzidx, const float* __restrict__ mask, int Wb)
{
    __shared__ int s_flo[Kb], s_nz[Kb];
    __shared__ int s_fmf[32], s_fxf[32];
    __shared__ int s_pmn[16], s_pwd[16];
    const int tid = threadIdx.x;
    {
        int n = 0;
        for (int w = 0; w < Wb; ++w) n += (mask[tid*Wb + w] > 0.5f);
        int flo = nzidx[tid*Wb];
        s_flo[tid] = flo; s_nz[tid] = n;
        if (blockIdx.x == 0) { g_flo[tid] = flo; g_nz[tid] = n; }
    }
    __syncthreads();

    if (tid < 32) {
        int f = blockIdx.x*32 + tid;
        int deg = 0, bl[4] = {0,0,0,0};
        int fmn = 1<<29, fmx = -1;
        if (f < Ff) {
            for (int k = 0; k < Kb; ++k) {
                int w = f - s_flo[k];
                if (w >= 0 && w < s_nz[k]) {
                    if (deg < 4) bl[deg] = k;
                    ++deg;
                    fmn = min(fmn, s_flo[k]);
                    fmx = max(fmx, s_flo[k] + s_nz[k]);
                }
            }
        }
        deg = min(deg, 4);
        if (f < NFP) {
            g_deg[f] = deg;
            #pragma unroll
            for (int i = 0; i < 4; ++i) g_bands[f*4+i] = bl[i];
        }
        s_fmf[tid] = deg ? fmn : (1<<29);
        s_fxf[tid] = deg ? fmx : -1;
    }
    __syncthreads();
    if (tid < 16) {
        int p = blockIdx.x*16 + tid;
        int fmn = min(s_fmf[2*tid], s_fmf[2*tid+1]);
        int fmx = max(s_fxf[2*tid], s_fxf[2*tid+1]);
        int w;
        if (fmx < 0) { fmn = 0; w = 0; }
        else         { w = min(fmx - fmn, MW); }
        if (p < NPAIR) { g_fmin2[p] = fmn; g_wid2[p] = w; }
        s_pmn[tid] = fmn; s_pwd[tid] = w;
    }
    __syncthreads();
    if (tid < 4) {
        int bc = blockIdx.x*4 + tid;           // block-col = 4 pairs = 8 f'
        int mn = 1<<29, mx = -1;
        #pragma unroll
        for (int i = 0; i < 4; ++i) {
            int pl = tid*4 + i;
            if (s_pwd[pl] > 0) {
                mn = min(mn, s_pmn[pl]);
                mx = max(mx, s_pmn[pl] + s_pwd[pl]);
            }
        }
        if (bc < NBCOL) {
            if (mx < 0) { g_bmin[bc] = 0; g_bwid[bc] = 0; }
            else        { g_bmin[bc] = mn; g_bwid[bc] = mx - mn; }
        }
    }
}

// ---------------------------------------------------------------------------
// k_weff: per-band fused W1@W2 (mel, 1/ola folded). grid (Kb, itiles of 16).
// ---------------------------------------------------------------------------
__global__ __launch_bounds__(256) void k_weff(
    const float* __restrict__ W1, const float* __restrict__ b1,
    const float* __restrict__ W2, const float* __restrict__ b2,
    const int*   __restrict__ nzidx, const float* __restrict__ nzmel,
    const float* __restrict__ ola, int Wb)
{
    __shared__ float W1s[16*Dd];
    __shared__ float cs[KEMAX];
    __shared__ float rs[16];
    __shared__ float b1s[Dd];

    const int k     = blockIdx.x;
    const int KeW   = 4*Wb;
    const int iBase = blockIdx.y * 16;
    const int tid   = threadIdx.x;

    const int nnz = g_nz[k];
    const int Ke4 = 4*nnz;
    if (iBase >= Ke4) return;
    const int ni = min(16, Ke4 - iBase);

    for (int j = tid; j < ni*Dd; j += 256)
        W1s[j] = W1[((size_t)k*KeW + iBase)*Dd + j];
    for (int w = tid; w < nnz; w += 256) {
        float inv = 1.0f / ola[nzidx[k*Wb + w]];
        cs[4*w+0]=inv; cs[4*w+1]=inv; cs[4*w+2]=inv; cs[4*w+3]=inv;
    }
    if (tid < ni) rs[tid] = nzmel[k*Wb + ((iBase + tid) >> 2)];
    if (tid < Dd) b1s[tid] = b1[k*Dd + tid];
    __syncthreads();

    const int nct = Ke4 >> 2, nrt = ni >> 2;
    if (tid < nrt*nct) {
        const int tr = tid / nct, tc = tid - tr*nct;
        ull acc[4][2] = {{0,0},{0,0},{0,0},{0,0}};
        const float* a = &W1s[(tr*4)*Dd];
        const float* w2base = W2 + (size_t)k*Dd*KeW + tc*4;
        #pragma unroll 4
        for (int d = 0; d < Dd; ++d) {
            ulonglong2 bv = *reinterpret_cast<const ulonglong2*>(w2base + (size_t)d*KeW);
            ull s;
            s = splat2(a[d]);      ffma2(acc[0][0], s, bv.x); ffma2(acc[0][1], s, bv.y);
            s = splat2(a[Dd+d]);   ffma2(acc[1][0], s, bv.x); ffma2(acc[1][1], s, bv.y);
            s = splat2(a[2*Dd+d]); ffma2(acc[2][0], s, bv.x); ffma2(acc[2][1], s, bv.y);
            s = splat2(a[3*Dd+d]); ffma2(acc[3][0], s, bv.x); ffma2(acc[3][1], s, bv.y);
        }
        const int gi = iBase + tr*4, go = tc*4;
        float4 c4 = *reinterpret_cast<const float4*>(&cs[go]);
        #pragma unroll
        for (int rr = 0; rr < 4; ++rr) {
            float v0,v1,v2,v3;
            unpack2(acc[rr][0], v0, v1);
            unpack2(acc[rr][1], v2, v3);
            float r = rs[tr*4+rr];
            float4 o4 = make_float4(v0*r*c4.x, v1*r*c4.y, v2*r*c4.z, v3*r*c4.w);
            *reinterpret_cast<float4*>(&g_Weff[((size_t)k*KeW + gi+rr)*KeW + go]) = o4;
        }
    }

    if (blockIdx.y == 0) {
        for (int o = tid; o < Ke4; o += 256) {
            float s = b2[(size_t)k*KeW + o];
            for (int d = 0; d < Dd; ++d) s += b1s[d] * W2[((size_t)k*Dd + d)*KeW + o];
            g_beff[k*KEMAX + o] = s * cs[o];
        }
    }
}

// ---------------------------------------------------------------------------
// k_scatter: assemble banded rows of M in pair-interleaved layout
//   g_M[((p*MW + j)*2 + s)*16 + c*4 + c2],  s = f&1
// ---------------------------------------------------------------------------
__global__ __launch_bounds__(256) void k_scatter(int Wb)
{
    const int f   = blockIdx.x;
    const int KeW = 4*Wb;
    const int p   = f >> 1;
    const int s   = f & 1;
    const int fm2 = g_fmin2[p];
    const int wid = g_wid2[p];
    const int deg = g_deg[f];
    __shared__ int s_k[4], s_flo4[4], s_nz4[4], s_wp[4];
    if (threadIdx.x < 4) {
        int i = threadIdx.x;
        int k = g_bands[f*4 + i];
        s_k[i]    = k;
        s_flo4[i] = g_flo[k];
        s_nz4[i]  = g_nz[k];
        s_wp[i]   = f - g_flo[k];
    }
    __syncthreads();

    for (int pos = threadIdx.x; pos < wid*4; pos += 256) {
        int j = pos >> 2;
        int c = pos & 3;
        int fbin = fm2 + j;
        float4 u[4];
        #pragma unroll
        for (int d = 0; d < 4; ++d) {
            int w = fbin - s_flo4[d];
            bool pv = (d < deg) && (w >= 0) && (w < s_nz4[d]);
            u[d] = pv ? *reinterpret_cast<const float4*>(
                     &g_Weff[((size_t)s_k[d]*KeW + 4*w + c)*KeW + 4*s_wp[d]])
                      : make_float4(0.f,0.f,0.f,0.f);
        }
        float4 v;
        v.x = (u[0].x + u[1].x) + (u[2].x + u[3].x);
        v.y = (u[0].y + u[1].y) + (u[2].y + u[3].y);
        v.z = (u[0].z + u[1].z) + (u[2].z + u[3].z);
        v.w = (u[0].w + u[1].w) + (u[2].w + u[3].w);
        *reinterpret_cast<float4*>(
            &g_M[(((size_t)p*MW + j)*2 + s)*16 + c*4]) = v;
    }
    if (threadIdx.x < 4) {
        float v = 0.0f;
        for (int d = 0; d < deg; ++d)
            v += g_beff[s_k[d]*KEMAX + 4*s_wp[d] + threadIdx.x];
        g_bias[f*4 + threadIdx.x] = v;
    }
}

// ---------------------------------------------------------------------------
// k_main: block = 64 rows x 8 f' (4 pairs), 128 threads, 2 blocks/SM.
// warp = 1 f'-pair; lane = 1 row-pair. Per-block M live ~20KB -> L1-resident
// (L1D = 228 - 157 = 71KB). launch_bounds(128,2) -> no register spills.
// ---------------------------------------------------------------------------
__global__ __launch_bounds__(128, 2) void k_main(
    const float* __restrict__ x, float* __restrict__ out, int sstr)
{
    extern __shared__ __align__(16) float smx[];   // [32 rowpairs][sstr floats]
    float* smo = smx;                              // aliases x region at epilogue

    const int tid   = threadIdx.x;
    const int wrp   = tid >> 5, lane = tid & 31;   // wrp 0..3
    const int f0    = blockIdx.x * 8;
    const int p0    = blockIdx.x * 4;
    const int row0  = blockIdx.y * 64;
    const int bmin  = g_bmin[blockIdx.x];
    const int bwid  = g_bwid[blockIdx.x];

    // staging: warp wrp stages rowpairs 8*wrp..8*wrp+7; lanes stride bins.
    #pragma unroll
    for (int q = 0; q < 8; ++q) {
        const int rp  = wrp*8 + q;
        const int rowE = row0 + 2*rp, rowO = rowE + 1;
        const int bE = rowE >> 9, tE = rowE & 511;
        const int bO = rowO >> 9, tO = rowO & 511;
        const float* xe = x + ((size_t)(bE*4)*512 + tE)*Ff + bmin;
        const float* xo = x + ((size_t)(bO*4)*512 + tO)*Ff + bmin;
        float* dst = smx + rp*sstr;
        for (int u = lane; u < bwid; u += 32) {
            float4 ve = make_float4(xe[u], xe[u+CSTR], xe[u+(size_t)2*CSTR], xe[u+(size_t)3*CSTR]);
            float4 vo = make_float4(xo[u], xo[u+CSTR], xo[u+(size_t)2*CSTR], xo[u+(size_t)3*CSTR]);
            *reinterpret_cast<float4*>(dst + u*8)     = ve;
            *reinterpret_cast<float4*>(dst + u*8 + 4) = vo;
        }
    }
    __syncthreads();

    const int p    = p0 + wrp;
    const int jmax = g_wid2[p];
    const int u0   = g_fmin2[p] - bmin;
    const int fA   = 2*p;

    const ulonglong2* mbase = reinterpret_cast<const ulonglong2*>(g_M + (size_t)p*MW*32);
    ulonglong2 bAv = *reinterpret_cast<const ulonglong2*>(&g_bias[fA*4]);
    ulonglong2 bBv = *reinterpret_cast<const ulonglong2*>(&g_bias[fA*4 + 4]);

    // acc[row2][f'2][c2pair2] as named regs
    ull aE00 = bAv.x, aE01 = bAv.y, aE10 = bBv.x, aE11 = bBv.y;
    ull aO00 = bAv.x, aO01 = bAv.y, aO10 = bBv.x, aO11 = bBv.y;

    const float* xp = smx + lane*sstr + u0*8;

    #pragma unroll 2
    for (int j = 0; j < jmax; ++j) {
        const ulonglong2* m = mbase + j*8;
        ulonglong2 m0 = m[0], m1 = m[1], m2 = m[2], m3 = m[3];
        ulonglong2 m4 = m[4], m5 = m[5], m6 = m[6], m7 = m[7];
        const float* xj = xp + j*8;
        float4 Xe = *reinterpret_cast<const float4*>(xj);
        float4 Xo = *reinterpret_cast<const float4*>(xj + 4);
        ull s;
        s = splat2(Xe.x);
        ffma2(aE00, s, m0.x); ffma2(aE01, s, m0.y);
        ffma2(aE10, s, m4.x); ffma2(aE11, s, m4.y);
        s = splat2(Xe.y);
        ffma2(aE00, s, m1.x); ffma2(aE01, s, m1.y);
        ffma2(aE10, s, m5.x); ffma2(aE11, s, m5.y);
        s = splat2(Xe.z);
        ffma2(aE00, s, m2.x); ffma2(aE01, s, m2.y);
        ffma2(aE10, s, m6.x); ffma2(aE11, s, m6.y);
        s = splat2(Xe.w);
        ffma2(aE00, s, m3.x); ffma2(aE01, s, m3.y);
        ffma2(aE10, s, m7.x); ffma2(aE11, s, m7.y);
        s = splat2(Xo.x);
        ffma2(aO00, s, m0.x); ffma2(aO01, s, m0.y);
        ffma2(aO10, s, m4.x); ffma2(aO11, s, m4.y);
        s = splat2(Xo.y);
        ffma2(aO00, s, m1.x); ffma2(aO01, s, m1.y);
        ffma2(aO10, s, m5.x); ffma2(aO11, s, m5.y);
        s = splat2(Xo.z);
        ffma2(aO00, s, m2.x); ffma2(aO01, s, m2.y);
        ffma2(aO10, s, m6.x); ffma2(aO11, s, m6.y);
        s = splat2(Xo.w);
        ffma2(aO00, s, m3.x); ffma2(aO01, s, m3.y);
        ffma2(aO10, s, m7.x); ffma2(aO11, s, m7.y);
    }

    __syncthreads();   // x tile dead; smo aliases smx

    // stage results: smo[row(64)][c2(4)*9 + fx(8)], row stride 37
    {
        int rowl = 2*lane;
        float v0,v1,v2,v3;
        #pragma unroll
        for (int g = 0; g < 2; ++g) {
            int fx = 2*wrp + g;
            ull a0 = g ? aE10 : aE00, a1 = g ? aE11 : aE01;
            unpack2(a0, v0, v1); unpack2(a1, v2, v3);
            smo[rowl*37 + 0*9 + fx] = v0;
            smo[rowl*37 + 1*9 + fx] = v1;
            smo[rowl*37 + 2*9 + fx] = v2;
            smo[rowl*37 + 3*9 + fx] = v3;
            ull b0 = g ? aO10 : aO00, b1 = g ? aO11 : aO01;
            unpack2(b0, v0, v1); unpack2(b1, v2, v3);
            smo[(rowl+1)*37 + 0*9 + fx] = v0;
            smo[(rowl+1)*37 + 1*9 + fx] = v1;
            smo[(rowl+1)*37 + 2*9 + fx] = v2;
            smo[(rowl+1)*37 + 3*9 + fx] = v3;
        }
    }
    __syncthreads();

    // coalesced store: warp wrp covers rows 16*wrp..16*wrp+15;
    // lanes: fx = lane&7, c2 = lane>>3 (32 outs per row).
    #pragma unroll
    for (int rr = 0; rr < 16; ++rr) {
        const int r   = wrp*16 + rr;
        const int row = row0 + r, b = row >> 9, t = row & 511;
        int fx  = lane & 7, cc2 = lane >> 3;
        int f = f0 + fx;
        if (f < Ff)
            out[((size_t)(b*4 + cc2)*512 + t)*Ff + f] = smo[r*37 + cc2*9 + fx];
    }
}

// ---------------------------------------------------------------------------
extern "C" void kernel_launch(void* const* d_in, const int* in_sizes, int n_in,
                              void* d_out, int out_size)
{
    const float* x     = (const float*)d_in[0];
    const float* W1    = (const float*)d_in[1];
    const float* b1    = (const float*)d_in[2];
    const float* W2    = (const float*)d_in[3];
    const float* b2    = (const float*)d_in[4];
    const int*   nzidx = (const int*)  d_in[5];
    const float* nzmel = (const float*)d_in[6];
    const float* mask  = (const float*)d_in[7];
    const float* ola   = (const float*)d_in[8];

    const int Wb = in_sizes[5] / Kb;

    k_finfo<<<33, 256>>>(nzidx, mask, Wb);

    int gy = (4*Wb + 15) / 16;
    k_weff<<<dim3(Kb, gy), 256>>>(W1, b1, W2, b2, nzidx, nzmel, ola, Wb);

    k_scatter<<<NFP, 256>>>(Wb);

    int xrange = 2*Wb + 8;                       // 8-f' block union bound
    int sstr = 8*xrange + 4;                     // floats per rowpair
    int main_smem = 32 * sstr * (int)sizeof(float);
    int smo_need = 64*37*(int)sizeof(float);
    if (main_smem < smo_need) main_smem = smo_need;
    cudaFuncSetAttribute(k_main, cudaFuncAttributeMaxDynamicSharedMemorySize, main_smem);
    k_main<<<dim3((Ff + 7)/8, NROWS/64), 128, main_smem>>>(x, (float*)d_out, sstr);
}

// round 13
// speedup vs baseline: 1.2485x; 1.2074x over previous
#include <cuda_runtime.h>
#include <stdint.h>

#define Kb     256
#define Dd     128
#define KEMAX  256
#define Ff     1025
#define NROWS  1024
#define CSTR   (512*1025)
#define MW     96
#define NFP    1056
#define NPAIR  528

typedef unsigned long long ull;

// ---- static device scratch ----
__device__ float g_Weff[(size_t)Kb*KEMAX*KEMAX];
__device__ float g_beff[Kb*KEMAX];
__device__ int   g_flo[Kb], g_nz[Kb];
__device__ int   g_fmin2[NPAIR], g_wid2[NPAIR];
__device__ float g_M[(size_t)NPAIR*MW*32];   // [pair][j][s(2)][c(4)][c2(4)]
__device__ float g_bias[NFP*4];

__device__ __forceinline__ ull splat2(float v) {
    ull r; asm("mov.b64 %0, {%1, %1};" : "=l"(r) : "f"(v)); return r;
}
__device__ __forceinline__ void ffma2(ull& d, ull a, ull b) {
    asm("fma.rn.f32x2 %0, %1, %2, %0;" : "+l"(d) : "l"(a), "l"(b));
}
__device__ __forceinline__ void unpack2(ull v, float& lo, float& hi) {
    asm("mov.b64 {%0, %1}, %2;" : "=f"(lo), "=f"(hi) : "l"(v));
}

// ---------------------------------------------------------------------------
// k_weff: per-band fused W1@W2 (mel, 1/ola folded). grid (Kb, itiles of 16).
// Self-sufficient: computes its band's nnz/flo; y==0 publishes g_nz/g_flo.
// ---------------------------------------------------------------------------
__global__ __launch_bounds__(256) void k_weff(
    const float* __restrict__ W1, const float* __restrict__ b1,
    const float* __restrict__ W2, const float* __restrict__ b2,
    const int*   __restrict__ nzidx, const float* __restrict__ nzmel,
    const float* __restrict__ mask,  const float* __restrict__ ola, int Wb)
{
    __shared__ float W1s[16*Dd];
    __shared__ float cs[KEMAX];
    __shared__ float rs[16];
    __shared__ float b1s[Dd];
    __shared__ int s_nnz;

    const int k     = blockIdx.x;
    const int KeW   = 4*Wb;
    const int iBase = blockIdx.y * 16;
    const int tid   = threadIdx.x;

    if (tid == 0) {
        int n = 0;
        for (int w = 0; w < Wb; ++w) n += (mask[k*Wb + w] > 0.5f);
        s_nnz = n;
        if (blockIdx.y == 0) { g_nz[k] = n; g_flo[k] = nzidx[k*Wb]; }
    }
    __syncthreads();

    const int nnz = s_nnz;
    const int Ke4 = 4*nnz;
    if (iBase >= Ke4) return;
    const int ni = min(16, Ke4 - iBase);

    for (int j = tid; j < ni*Dd; j += 256)
        W1s[j] = W1[((size_t)k*KeW + iBase)*Dd + j];
    for (int w = tid; w < nnz; w += 256) {
        float inv = 1.0f / ola[nzidx[k*Wb + w]];
        cs[4*w+0]=inv; cs[4*w+1]=inv; cs[4*w+2]=inv; cs[4*w+3]=inv;
    }
    if (tid < ni) rs[tid] = nzmel[k*Wb + ((iBase + tid) >> 2)];
    if (tid < Dd) b1s[tid] = b1[k*Dd + tid];
    __syncthreads();

    const int nct = Ke4 >> 2, nrt = ni >> 2;
    if (tid < nrt*nct) {
        const int tr = tid / nct, tc = tid - tr*nct;
        ull acc[4][2] = {{0,0},{0,0},{0,0},{0,0}};
        const float* a = &W1s[(tr*4)*Dd];
        const float* w2base = W2 + (size_t)k*Dd*KeW + tc*4;
        #pragma unroll 4
        for (int d = 0; d < Dd; ++d) {
            ulonglong2 bv = *reinterpret_cast<const ulonglong2*>(w2base + (size_t)d*KeW);
            ull s;
            s = splat2(a[d]);      ffma2(acc[0][0], s, bv.x); ffma2(acc[0][1], s, bv.y);
            s = splat2(a[Dd+d]);   ffma2(acc[1][0], s, bv.x); ffma2(acc[1][1], s, bv.y);
            s = splat2(a[2*Dd+d]); ffma2(acc[2][0], s, bv.x); ffma2(acc[2][1], s, bv.y);
            s = splat2(a[3*Dd+d]); ffma2(acc[3][0], s, bv.x); ffma2(acc[3][1], s, bv.y);
        }
        const int gi = iBase + tr*4, go = tc*4;
        float4 c4 = *reinterpret_cast<const float4*>(&cs[go]);
        #pragma unroll
        for (int rr = 0; rr < 4; ++rr) {
            float v0,v1,v2,v3;
            unpack2(acc[rr][0], v0, v1);
            unpack2(acc[rr][1], v2, v3);
            float r = rs[tr*4+rr];
            float4 o4 = make_float4(v0*r*c4.x, v1*r*c4.y, v2*r*c4.z, v3*r*c4.w);
            *reinterpret_cast<float4*>(&g_Weff[((size_t)k*KeW + gi+rr)*KeW + go]) = o4;
        }
    }

    if (blockIdx.y == 0) {
        for (int o = tid; o < Ke4; o += 256) {
            float s = b2[(size_t)k*KeW + o];
            for (int d = 0; d < Dd; ++d) s += b1s[d] * W2[((size_t)k*Dd + d)*KeW + o];
            g_beff[k*KEMAX + o] = s * cs[o];
        }
    }
}

// ---------------------------------------------------------------------------
// k_scatter: fused band-scan (ballot over 256 bands, deterministic order)
// + banded-M assembly in pair-interleaved layout
//   g_M[((p*MW + j)*2 + s)*16 + c*4 + c2],  s = f&1
// Also writes g_fmin2/g_wid2 (both pair members write identical values).
// ---------------------------------------------------------------------------
__global__ __launch_bounds__(256) void k_scatter(int Wb)
{
    const int f   = blockIdx.x;
    const int KeW = 4*Wb;
    const int p   = f >> 1;
    const int s   = f & 1;
    const int tid = threadIdx.x;

    __shared__ int s_flo[Kb], s_nz[Kb];
    __shared__ int s_k[4], s_flo4[4], s_nz4[4], s_wp[4];
    __shared__ int s_info[3];   // deg, fm2, wid

    s_flo[tid] = g_flo[tid];
    s_nz[tid]  = g_nz[tid];
    __syncthreads();

    if (tid < 32) {
        const int fo = f ^ 1;
        int fmn = 1<<29, fmx = -1;
        int deg = 0;
        for (int w = 0; w < 8; ++w) {
            int k   = w*32 + tid;
            int flo = s_flo[k], nz = s_nz[k];
            bool cs = (f  < Ff) && (f  >= flo) && (f  < flo + nz);
            bool co = (fo < Ff) && (fo >= flo) && (fo < flo + nz);
            if (cs | co) { fmn = min(fmn, flo); fmx = max(fmx, flo + nz); }
            unsigned bs = __ballot_sync(0xffffffffu, cs);
            if (tid == 0) {
                while (bs) {
                    int b = __ffs(bs) - 1; bs &= bs - 1;
                    if (deg < 4) {
                        int kk = w*32 + b;
                        s_k[deg]    = kk;
                        s_flo4[deg] = s_flo[kk];
                        s_nz4[deg]  = s_nz[kk];
                        s_wp[deg]   = f - s_flo[kk];
                        ++deg;
                    }
                }
            }
        }
        #pragma unroll
        for (int off = 16; off; off >>= 1) {
            fmn = min(fmn, __shfl_xor_sync(0xffffffffu, fmn, off));
            fmx = max(fmx, __shfl_xor_sync(0xffffffffu, fmx, off));
        }
        if (tid == 0) {
            // default-fill unused band slots (predicated out below, but keep sane)
            for (int d = deg; d < 4; ++d) { s_k[d]=0; s_flo4[d]=1<<29; s_nz4[d]=0; s_wp[d]=0; }
            int fm2, wid;
            if (fmx < 0) { fm2 = 0; wid = 0; }
            else         { fm2 = fmn; wid = min(fmx - fmn, MW); }
            g_fmin2[p] = fm2;
            g_wid2[p]  = wid;
            s_info[0] = deg; s_info[1] = fm2; s_info[2] = wid;
        }
    }
    __syncthreads();

    const int deg = s_info[0], fm2 = s_info[1], wid = s_info[2];

    for (int pos = tid; pos < wid*4; pos += 256) {
        int j = pos >> 2;
        int c = pos & 3;
        int fbin = fm2 + j;
        float4 u[4];
        #pragma unroll
        for (int d = 0; d < 4; ++d) {
            int w = fbin - s_flo4[d];
            bool pv = (d < deg) && (w >= 0) && (w < s_nz4[d]);
            u[d] = pv ? *reinterpret_cast<const float4*>(
                     &g_Weff[((size_t)s_k[d]*KeW + 4*w + c)*KeW + 4*s_wp[d]])
                      : make_float4(0.f,0.f,0.f,0.f);
        }
        float4 v;
        v.x = (u[0].x + u[1].x) + (u[2].x + u[3].x);
        v.y = (u[0].y + u[1].y) + (u[2].y + u[3].y);
        v.z = (u[0].z + u[1].z) + (u[2].z + u[3].z);
        v.w = (u[0].w + u[1].w) + (u[2].w + u[3].w);
        *reinterpret_cast<float4*>(
            &g_M[(((size_t)p*MW + j)*2 + s)*16 + c*4]) = v;
    }
    if (tid < 4) {
        float v = 0.0f;
        for (int d = 0; d < deg; ++d)
            v += g_beff[s_k[d]*KEMAX + 4*s_wp[d] + tid];
        g_bias[f*4 + tid] = v;
    }
}

// ---------------------------------------------------------------------------
// k_main: block = 64 rows x 16 f'; warp = 1 f'-pair; lane = 1 row-pair.
// (R8 configuration — best measured.) bmin/bwid reduced in-kernel.
// ---------------------------------------------------------------------------
__global__ __launch_bounds__(256, 2) void k_main(
    const float* __restrict__ x, float* __restrict__ out, int sstr)
{
    extern __shared__ __align__(16) float smx[];   // [32 rowpairs][sstr floats]
    float* smo = smx;                              // aliases (x dead at epilogue)
    __shared__ int sbm[2];

    const int tid   = threadIdx.x;
    const int wrp   = tid >> 5, lane = tid & 31;
    const int f0    = blockIdx.x * 16;
    const int p0    = f0 >> 1;
    const int row0  = blockIdx.y * 64;

    if (tid < 8) {
        int pq = p0 + tid;
        int wq = g_wid2[pq];
        int mn = wq > 0 ? g_fmin2[pq]      : (1<<29);
        int mx = wq > 0 ? g_fmin2[pq] + wq : -1;
        #pragma unroll
        for (int off = 4; off; off >>= 1) {
            mn = min(mn, __shfl_xor_sync(0xffu, mn, off));
            mx = max(mx, __shfl_xor_sync(0xffu, mx, off));
        }
        if (tid == 0) {
            sbm[0] = (mx < 0) ? 0 : mn;
            sbm[1] = (mx < 0) ? 0 : (mx - mn);
        }
    }
    __syncthreads();
    const int bmin = sbm[0];
    const int bwid = sbm[1];

    // staging: warp wrp stages rowpairs 4*wrp..4*wrp+3; lanes stride bins.
    #pragma unroll
    for (int q = 0; q < 4; ++q) {
        const int rp  = wrp*4 + q;
        const int rowE = row0 + 2*rp, rowO = rowE + 1;
        const int bE = rowE >> 9, tE = rowE & 511;
        const int bO = rowO >> 9, tO = rowO & 511;
        const float* xe = x + ((size_t)(bE*4)*512 + tE)*Ff + bmin;
        const float* xo = x + ((size_t)(bO*4)*512 + tO)*Ff + bmin;
        float* dst = smx + rp*sstr;
        for (int u = lane; u < bwid; u += 32) {
            float4 ve = make_float4(xe[u], xe[u+CSTR], xe[u+(size_t)2*CSTR], xe[u+(size_t)3*CSTR]);
            float4 vo = make_float4(xo[u], xo[u+CSTR], xo[u+(size_t)2*CSTR], xo[u+(size_t)3*CSTR]);
            *reinterpret_cast<float4*>(dst + u*8)     = ve;
            *reinterpret_cast<float4*>(dst + u*8 + 4) = vo;
        }
    }
    __syncthreads();

    const int p    = p0 + wrp;
    const int jmax = g_wid2[p];
    const int u0   = g_fmin2[p] - bmin;
    const int fA   = 2*p;

    const ulonglong2* mbase = reinterpret_cast<const ulonglong2*>(g_M + (size_t)p*MW*32);
    ulonglong2 bAv = *reinterpret_cast<const ulonglong2*>(&g_bias[fA*4]);
    ulonglong2 bBv = *reinterpret_cast<const ulonglong2*>(&g_bias[fA*4 + 4]);

    ull aE00 = bAv.x, aE01 = bAv.y, aE10 = bBv.x, aE11 = bBv.y;
    ull aO00 = bAv.x, aO01 = bAv.y, aO10 = bBv.x, aO11 = bBv.y;

    const float* xp = smx + lane*sstr + u0*8;

    #pragma unroll 2
    for (int j = 0; j < jmax; ++j) {
        const ulonglong2* m = mbase + j*8;
        ulonglong2 m0 = m[0], m1 = m[1], m2 = m[2], m3 = m[3];
        ulonglong2 m4 = m[4], m5 = m[5], m6 = m[6], m7 = m[7];
        const float* xj = xp + j*8;
        float4 Xe = *reinterpret_cast<const float4*>(xj);
        float4 Xo = *reinterpret_cast<const float4*>(xj + 4);
        ull s;
        s = splat2(Xe.x);
        ffma2(aE00, s, m0.x); ffma2(aE01, s, m0.y);
        ffma2(aE10, s, m4.x); ffma2(aE11, s, m4.y);
        s = splat2(Xe.y);
        ffma2(aE00, s, m1.x); ffma2(aE01, s, m1.y);
        ffma2(aE10, s, m5.x); ffma2(aE11, s, m5.y);
        s = splat2(Xe.z);
        ffma2(aE00, s, m2.x); ffma2(aE01, s, m2.y);
        ffma2(aE10, s, m6.x); ffma2(aE11, s, m6.y);
        s = splat2(Xe.w);
        ffma2(aE00, s, m3.x); ffma2(aE01, s, m3.y);
        ffma2(aE10, s, m7.x); ffma2(aE11, s, m7.y);
        s = splat2(Xo.x);
        ffma2(aO00, s, m0.x); ffma2(aO01, s, m0.y);
        ffma2(aO10, s, m4.x); ffma2(aO11, s, m4.y);
        s = splat2(Xo.y);
        ffma2(aO00, s, m1.x); ffma2(aO01, s, m1.y);
        ffma2(aO10, s, m5.x); ffma2(aO11, s, m5.y);
        s = splat2(Xo.z);
        ffma2(aO00, s, m2.x); ffma2(aO01, s, m2.y);
        ffma2(aO10, s, m6.x); ffma2(aO11, s, m6.y);
        s = splat2(Xo.w);
        ffma2(aO00, s, m3.x); ffma2(aO01, s, m3.y);
        ffma2(aO10, s, m7.x); ffma2(aO11, s, m7.y);
    }

    __syncthreads();   // x tile dead; smo aliases smx

    // stage results: smo[row(64)][c2(4)*17 + fx(16)]
    {
        int rowl = 2*lane;
        float v0,v1,v2,v3;
        #pragma unroll
        for (int g = 0; g < 2; ++g) {
            int fx = 2*wrp + g;
            ull a0 = g ? aE10 : aE00, a1 = g ? aE11 : aE01;
            unpack2(a0, v0, v1); unpack2(a1, v2, v3);
            smo[rowl*69 + 0*17 + fx] = v0;
            smo[rowl*69 + 1*17 + fx] = v1;
            smo[rowl*69 + 2*17 + fx] = v2;
            smo[rowl*69 + 3*17 + fx] = v3;
            ull b0 = g ? aO10 : aO00, b1 = g ? aO11 : aO01;
            unpack2(b0, v0, v1); unpack2(b1, v2, v3);
            smo[(rowl+1)*69 + 0*17 + fx] = v0;
            smo[(rowl+1)*69 + 1*17 + fx] = v1;
            smo[(rowl+1)*69 + 2*17 + fx] = v2;
            smo[(rowl+1)*69 + 3*17 + fx] = v3;
        }
    }
    __syncthreads();

    // coalesced store: warp wrp covers rows 8*wrp..8*wrp+7
    #pragma unroll
    for (int rr = 0; rr < 8; ++rr) {
        const int r   = wrp*8 + rr;
        const int row = row0 + r, b = row >> 9, t = row & 511;
        #pragma unroll
        for (int h = 0; h < 2; ++h) {
            int e   = h*32 + lane;          // 0..63
            int fx  = e & 15, cc2 = e >> 4;
            int f = f0 + fx;
            if (f < Ff)
                out[((size_t)(b*4 + cc2)*512 + t)*Ff + f] = smo[r*69 + cc2*17 + fx];
        }
    }
}

// ---------------------------------------------------------------------------
extern "C" void kernel_launch(void* const* d_in, const int* in_sizes, int n_in,
                              void* d_out, int out_size)
{
    const float* x     = (const float*)d_in[0];
    const float* W1    = (const float*)d_in[1];
    const float* b1    = (const float*)d_in[2];
    const float* W2    = (const float*)d_in[3];
    const float* b2    = (const float*)d_in[4];
    const int*   nzidx = (const int*)  d_in[5];
    const float* nzmel = (const float*)d_in[6];
    const float* mask  = (const float*)d_in[7];
    const float* ola   = (const float*)d_in[8];

    const int Wb = in_sizes[5] / Kb;

    int gy = (4*Wb + 15) / 16;
    k_weff<<<dim3(Kb, gy), 256>>>(W1, b1, W2, b2, nzidx, nzmel, mask, ola, Wb);

    k_scatter<<<NFP, 256>>>(Wb);

    int xrange = 2*Wb + 16;
    int sstr = 8*xrange + 4;                     // floats per rowpair
    int main_smem = 32 * sstr * (int)sizeof(float);
    int smo_need = 64*69*(int)sizeof(float);
    if (main_smem < smo_need) main_smem = smo_need;
    cudaFuncSetAttribute(k_main, cudaFuncAttributeMaxDynamicSharedMemorySize, main_smem);
    k_main<<<dim3((Ff + 15)/16, NROWS/64), 256, main_smem>>>(x, (float*)d_out, sstr);
}